// round 15
// baseline (speedup 1.0000x reference)
#include <cuda_runtime.h>
#include <cuda_fp16.h>
#include <cstdint>
#include <cstddef>

#define DEV __device__ __forceinline__

// ---------------- scratch (static device allocations: allowed) ----------------
__device__ __half g_W0h[4096u * 1024u];  // 8 MB, W0^T [out=4096][in=1024] fp16
__device__ __half g_W1h[1024u * 4096u];  // 8 MB, W1^T [out=1024][in=4096] fp16
__device__ __half g_Xh [8192u * 1024u];  // 16 MB, fp16 x
__device__ __half g_Hh [8192u * 4096u];  // 64 MB, fp16 gelu(h)

// ---------------- helpers ----------------
DEV uint32_t smem_u32(const void* p) { return (uint32_t)__cvta_generic_to_shared(p); }
DEV void cp_async16(uint32_t dst, const void* src) {
    asm volatile("cp.async.cg.shared.global [%0], [%1], 16;\n" :: "r"(dst), "l"(src));
}
DEV void cp_commit() { asm volatile("cp.async.commit_group;\n" ::: "memory"); }
template <int W> DEV void cp_wait() {
    asm volatile("cp.async.wait_group %0;\n" :: "n"(W) : "memory");
}
DEV void mma_f16(float* c, const uint32_t* a, const uint32_t b0, const uint32_t b1) {
    asm volatile(
        "mma.sync.aligned.m16n8k16.row.col.f32.f16.f16.f32 "
        "{%0,%1,%2,%3}, {%4,%5,%6,%7}, {%8,%9}, {%0,%1,%2,%3};\n"
        : "+f"(c[0]), "+f"(c[1]), "+f"(c[2]), "+f"(c[3])
        : "r"(a[0]), "r"(a[1]), "r"(a[2]), "r"(a[3]), "r"(b0), "r"(b1));
}
DEV void ldsm_x4(uint32_t* r, uint32_t addr) {
    asm volatile("ldmatrix.sync.aligned.m8n8.x4.shared.b16 {%0,%1,%2,%3}, [%4];"
                 : "=r"(r[0]), "=r"(r[1]), "=r"(r[2]), "=r"(r[3]) : "r"(addr));
}
// exact-erf gelu via the cheap erff polynomial path
DEV float gelu_exact(float x) {
    return 0.5f * x * (1.0f + erff(x * 0.70710678118654752f));
}

// ---------------- fused prologue ----------------
// blocks [0,1024)        : x fp32 -> fp16 (2 float4 -> 1 uint4, 4 per thread)
// blocks [1024,1280)     : build W0^T rows for (p,q); bc once, 16 o-rows
// blocks [1280,1408)     : build W1^T rows for (p,q); bc once, 8 o-rows
// __launch_bounds__(256,4) caps regs at 64 so the HBM-streaming convert blocks
// run at 4 CTAs/SM (Round-14 lesson: 160 regs -> occ 12% -> latency-starved).
constexpr int PB_X = 1024, PB_W0 = 256, PB_W1 = 128;
constexpr int PB_TOTAL = PB_X + PB_W0 + PB_W1;

union H2x4 {
    uint4 u;
    __half2 h[4];
};

__global__ void __launch_bounds__(256, 4)
k_prologue(const float4* __restrict__ x,
           const float* __restrict__ c0a, const float* __restrict__ c0b,
           const float* __restrict__ c0c,
           const float* __restrict__ c1a, const float* __restrict__ c1b,
           const float* __restrict__ c1c) {
    const int bid = blockIdx.x;
    const int t = threadIdx.x;

    if (bid < PB_X) {
        // ---- x fp32 -> fp16, 16B stores
        uint4* xh4 = reinterpret_cast<uint4*>(g_Xh);
#pragma unroll
        for (int kk = 0; kk < 4; kk++) {
            int idx = bid * 1024 + kk * 256 + t;       // < 1M
            float4 v0 = x[2 * idx];
            float4 v1 = x[2 * idx + 1];
            H2x4 o;
            o.h[0] = __floats2half2_rn(v0.x, v0.y);
            o.h[1] = __floats2half2_rn(v0.z, v0.w);
            o.h[2] = __floats2half2_rn(v1.x, v1.y);
            o.h[3] = __floats2half2_rn(v1.z, v1.w);
            xh4[idx] = o.u;
        }
    } else if (bid < PB_X + PB_W0) {
        // ---- W0t[(o*16+p)*16+q][(i*16+j)*8+k] = sum_r a[i,o,r] * bc[(r*16+j)*8+k]
        __shared__ float a_sh[1024], b_sh[1024], c_sh[64], bc[1024];
        const int pq = bid - PB_X;
        const int p = pq >> 4, q = pq & 15;

        for (int idx = t; idx < 1024; idx += 256) {
            a_sh[idx] = c0a[idx];                            // a[(i*16+o)*8+r]
            b_sh[idx] = c0b[(idx >> 3) * 128 + p * 8 + (idx & 7)]; // b[(rj)*8+s]
        }
        if (t < 64) {                                        // c_sh[s*8+k]
            int s = t >> 3, k = t & 7;
            c_sh[t] = c0c[(s * 8 + k) * 16 + q];
        }
        __syncthreads();
        for (int idx = t; idx < 1024; idx += 256) {          // bc[(rj)*8+k]
            int rj = idx >> 3, k = idx & 7;
            float acc = 0.f;
#pragma unroll
            for (int s = 0; s < 8; s++) acc = fmaf(b_sh[rj * 8 + s], c_sh[s * 8 + k], acc);
            bc[idx] = acc;
        }
        __syncthreads();
        const int n0 = 4 * t;
        const int i = n0 >> 7, j = (n0 >> 3) & 15;           // k = 0..3 (since n0%8==0..4)
#pragma unroll 1
        for (int o = 0; o < 16; o++) {
            const int m = (o * 16 + p) * 16 + q;
            __half2* dst = reinterpret_cast<__half2*>(&g_W0h[(size_t)m * 1024 + n0]);
#pragma unroll
            for (int d2 = 0; d2 < 2; d2++) {                 // 2 outputs per pass
                float v0 = 0.f, v1 = 0.f;
                const int kbase = (n0 & 7) + 2 * d2;
#pragma unroll
                for (int r = 0; r < 8; r++) {
                    const float av = a_sh[(i * 16 + o) * 8 + r];
                    v0 = fmaf(av, bc[(r * 16 + j) * 8 + kbase],     v0);
                    v1 = fmaf(av, bc[(r * 16 + j) * 8 + kbase + 1], v1);
                }
                dst[d2] = __floats2half2_rn(v0, v1);
            }
        }
    } else {
        // ---- W1t[(o*16+p)*8+q][(i*16+j)*16+k] = sum_r a[i,o,r] * bc[(r*16+j)*16+k]
        __shared__ float a_sh1[1024], b_sh1[1024], c_sh1[128], bc1[2048];
        const int pq = bid - (PB_X + PB_W0);
        const int p = pq >> 3, q = pq & 7;

        for (int idx = t; idx < 1024; idx += 256) {
            a_sh1[idx] = c1a[idx];                           // a[(i*8+o)*8+r]
            b_sh1[idx] = c1b[(idx >> 3) * 128 + p * 8 + (idx & 7)];
        }
        if (t < 128) {                                       // c_sh[s*16+k]
            int s = t >> 4, k = t & 15;
            c_sh1[t] = c1c[(s * 16 + k) * 8 + q];
        }
        __syncthreads();
        for (int idx = t; idx < 2048; idx += 256) {          // bc[(rj)*16+k]
            int rj = idx >> 4, k = idx & 15;
            float acc = 0.f;
#pragma unroll
            for (int s = 0; s < 8; s++) acc = fmaf(b_sh1[rj * 8 + s], c_sh1[s * 16 + k], acc);
            bc1[idx] = acc;
        }
        __syncthreads();
        const int i = t >> 4, j = t & 15;                    // n = 16t + k
#pragma unroll 1
        for (int o = 0; o < 8; o++) {
            const int m = (o * 16 + p) * 8 + q;
            __half2* dst = reinterpret_cast<__half2*>(&g_W1h[(size_t)m * 4096 + 16 * t]);
#pragma unroll 1
            for (int k2 = 0; k2 < 8; k2++) {                 // 2 outputs per pass
                float v0 = 0.f, v1 = 0.f;
#pragma unroll
                for (int r = 0; r < 8; r++) {
                    const float av = a_sh1[(i * 8 + o) * 8 + r];
                    v0 = fmaf(av, bc1[(r * 16 + j) * 16 + 2 * k2],     v0);
                    v1 = fmaf(av, bc1[(r * 16 + j) * 16 + 2 * k2 + 1], v1);
                }
                dst[k2] = __floats2half2_rn(v0, v1);
            }
        }
    }
}

// ---------------- fp16 GEMM: C = act(A @ B^T + bias) ----------------
// CTA tile 128(M) x 256(N), BK=64 halves, 3-stage cp.async ring.
// 256 threads = 8 warps in 2(M) x 4(N); warp tile 64x64 (acc 128 regs).
// At the legacy-HMMA instruction-rate ceiling; unchanged from Round 10-14 best.
constexpr int BM = 128, BN = 256, BKH = 64, STAGES = 3;
constexpr int STRW = 36;                               // 32 words + 4 pad
constexpr int ROWB = STRW * 4;                         // 144 B row stride
constexpr int A_WORDS = BM * STRW;                     // 4608
constexpr int B_WORDS = BN * STRW;                     // 9216
constexpr int STAGE_WORDS = A_WORDS + B_WORDS;         // 13824
constexpr int STAGE_BYTES = STAGE_WORDS * 4;           // 55296
constexpr uint32_t STAGE_LAST = 2u * STAGE_BYTES;
constexpr int GEMM_SMEM = STAGES * STAGE_BYTES;        // 165888 B

template <bool FUSE_GELU, bool HALF_OUT>
__global__ void __launch_bounds__(256, 1)
k_gemm_f16(const __half* __restrict__ A, const __half* __restrict__ Bg,
           const float* __restrict__ bias, void* __restrict__ Cv,
           int M, int N, int K) {
    extern __shared__ uint32_t smem_w[];
    const uint32_t sbase = smem_u32(smem_w);

    const int tid = threadIdx.x;
    const int m0 = blockIdx.y * BM;
    const int n0 = blockIdx.x * BN;
    const int lane = tid & 31;
    const int warp = tid >> 5;
    const int g = lane >> 2, tig = lane & 3;
    const int wm = (warp & 1) * 64;        // 2 warps in M
    const int wn = (warp >> 1) * 64;       // 4 warps in N

    const int T = K / BKH;

    // ---- cp.async mapping: 384 rows x 128B per stage = 3072 x 16B chunks ----
    const int r0 = tid >> 3;
    const int cwB = (tid & 7) * 16;                 // byte offset within row
    const __half* aNext = A + (size_t)(m0 + r0) * K + (tid & 7) * 8;
    const __half* bNext = Bg + (size_t)(n0 + r0) * K + (tid & 7) * 8;
    const uint32_t sa_off = (uint32_t)(r0 * ROWB) + (uint32_t)cwB;
    const uint32_t sb_off = (uint32_t)A_WORDS * 4u + sa_off;

    auto issue_at = [&](uint32_t stoff) {
        const uint32_t sa = sbase + stoff + sa_off;
        const uint32_t sb = sbase + stoff + sb_off;
#pragma unroll
        for (int i = 0; i < 4; i++)
            cp_async16(sa + (uint32_t)(32 * i * ROWB), aNext + (size_t)(32 * i) * K);
#pragma unroll
        for (int i = 0; i < 8; i++)
            cp_async16(sb + (uint32_t)(32 * i * ROWB), bNext + (size_t)(32 * i) * K);
        cp_commit();
        aNext += BKH;
        bNext += BKH;
    };

    // ldmatrix base addresses (stage 0)
    const uint32_t aLdsm = sbase
        + (uint32_t)((wm + (lane & 15)) * ROWB)
        + (uint32_t)((lane >> 4) * 16);
    const uint32_t bLdsm = sbase + (uint32_t)A_WORDS * 4u
        + (uint32_t)((wn + ((lane >> 4) << 3) + (lane & 7)) * ROWB)
        + (uint32_t)(((lane >> 3) & 1) * 16);

    float acc[4][8][4];
#pragma unroll
    for (int mi = 0; mi < 4; mi++)
#pragma unroll
        for (int ni = 0; ni < 8; ni++)
#pragma unroll
            for (int q = 0; q < 4; q++) acc[mi][ni][q] = 0.f;

    issue_at(0);
    issue_at(STAGE_BYTES);

    uint32_t stoff_i = STAGE_LAST;    // smem offset for next issue (stage t+2)
    uint32_t stoff_c = 0;             // smem offset for current compute (stage t)

    uint32_t af[2][4][4];             // double-buffered A frags (4 m16k16)
    uint32_t bq[2][4][4];             // double-buffered B frags (8 n8k16)

    for (int t = 0; t < T; ++t) {
        cp_wait<1>();                 // stage t landed
        __syncthreads();              // all reads of the buffer being refilled done

        const uint32_t aS = aLdsm + stoff_c;
        const uint32_t bS = bLdsm + stoff_c;
        stoff_c = (stoff_c == STAGE_LAST) ? 0u : stoff_c + (uint32_t)STAGE_BYTES;

        // prime k16=0 fragments immediately after the barrier
#pragma unroll
        for (int nip = 0; nip < 4; ++nip)
            ldsm_x4(bq[0][nip], bS + (uint32_t)(nip * 16 * ROWB));
#pragma unroll
        for (int mi = 0; mi < 4; ++mi)
            ldsm_x4(af[0][mi], aS + (uint32_t)(mi * 16 * ROWB));

        if (t + 2 < T) issue_at(stoff_i);
        stoff_i = (stoff_i == STAGE_LAST) ? 0u : stoff_i + (uint32_t)STAGE_BYTES;

#pragma unroll
        for (int k16 = 0; k16 < 4; ++k16) {
            const int cur = k16 & 1, nxt = cur ^ 1;
            if (k16 < 3) {            // prefetch next k16's fragments
                const uint32_t kb = (uint32_t)((k16 + 1) * 32);
#pragma unroll
                for (int nip = 0; nip < 4; ++nip)
                    ldsm_x4(bq[nxt][nip], bS + (uint32_t)(nip * 16 * ROWB) + kb);
#pragma unroll
                for (int mi = 0; mi < 4; ++mi)
                    ldsm_x4(af[nxt][mi], aS + (uint32_t)(mi * 16 * ROWB) + kb);
            }
#pragma unroll
            for (int mi = 0; mi < 4; ++mi)
#pragma unroll
                for (int ni = 0; ni < 8; ++ni)
                    mma_f16(acc[mi][ni], af[cur][mi], bq[cur][ni >> 1][2 * (ni & 1)],
                            bq[cur][ni >> 1][2 * (ni & 1) + 1]);
        }
    }

    // ---- epilogue ----
#pragma unroll
    for (int mi = 0; mi < 4; ++mi) {
        const int row = m0 + wm + mi * 16 + g;
#pragma unroll
        for (int ni = 0; ni < 8; ++ni) {
            const int col = n0 + wn + ni * 8 + tig * 2;
            const float bv0 = bias[col], bv1 = bias[col + 1];
            float v00 = acc[mi][ni][0] + bv0;
            float v01 = acc[mi][ni][1] + bv1;
            float v10 = acc[mi][ni][2] + bv0;
            float v11 = acc[mi][ni][3] + bv1;
            if (FUSE_GELU) {
                v00 = gelu_exact(v00);
                v01 = gelu_exact(v01);
                v10 = gelu_exact(v10);
                v11 = gelu_exact(v11);
            }
            if (HALF_OUT) {
                __half* C = (__half*)Cv;
                *reinterpret_cast<__half2*>(&C[(size_t)row * N + col]) =
                    __floats2half2_rn(v00, v01);
                *reinterpret_cast<__half2*>(&C[(size_t)(row + 8) * N + col]) =
                    __floats2half2_rn(v10, v11);
            } else {
                float* C = (float*)Cv;
                *reinterpret_cast<float2*>(&C[(size_t)row * N + col])       = make_float2(v00, v01);
                *reinterpret_cast<float2*>(&C[(size_t)(row + 8) * N + col]) = make_float2(v10, v11);
            }
        }
    }
}

// ---------------- launch ----------------
extern "C" void kernel_launch(void* const* d_in, const int* in_sizes, int n_in,
                              void* d_out, int out_size) {
    const float* x   = (const float*)d_in[0];
    const float* c0a = (const float*)d_in[1];
    const float* c0b = (const float*)d_in[2];
    const float* c0c = (const float*)d_in[3];
    const float* b0  = (const float*)d_in[4];
    const float* c1a = (const float*)d_in[5];
    const float* c1b = (const float*)d_in[6];
    const float* c1c = (const float*)d_in[7];
    const float* b1  = (const float*)d_in[8];
    float* out = (float*)d_out;

    void *pW0, *pW1, *pXh, *pHh;
    cudaGetSymbolAddress(&pW0, g_W0h);
    cudaGetSymbolAddress(&pW1, g_W1h);
    cudaGetSymbolAddress(&pXh, g_Xh);
    cudaGetSymbolAddress(&pHh, g_Hh);
    __half* W0h = (__half*)pW0;
    __half* W1h = (__half*)pW1;
    __half* Xh  = (__half*)pXh;
    __half* Hh  = (__half*)pHh;

    cudaFuncSetAttribute(k_gemm_f16<true, true>,
                         cudaFuncAttributeMaxDynamicSharedMemorySize, GEMM_SMEM);
    cudaFuncSetAttribute(k_gemm_f16<false, false>,
                         cudaFuncAttributeMaxDynamicSharedMemorySize, GEMM_SMEM);

    // 1) fused prologue: x->fp16 + both transposed TT weight matrices (dedup'd, 64-reg)
    k_prologue<<<PB_TOTAL, 256>>>((const float4*)x, c0a, c0b, c0c, c1a, c1b, c1c);
    // 2) Hh = fp16(gelu(Xh @ W0h^T + b0))   [8192 x 4096]
    k_gemm_f16<true, true><<<dim3(4096 / BN, 8192 / BM), 256, GEMM_SMEM>>>(
        Xh, W0h, b0, Hh, 8192, 4096, 1024);
    // 3) out = Hh @ W1h^T + b1              [8192 x 1024] fp32
    k_gemm_f16<false, false><<<dim3(1024 / BN, 8192 / BM), 256, GEMM_SMEM>>>(
        Hh, W1h, b1, out, 8192, 1024, 4096);
}

// round 16
// speedup vs baseline: 1.1799x; 1.1799x over previous
#include <cuda_runtime.h>
#include <cuda_fp16.h>
#include <cstdint>
#include <cstddef>

#define DEV __device__ __forceinline__

// ---------------- scratch (static device allocations: allowed) ----------------
__device__ __half g_W0h[4096u * 1024u];  // 8 MB, W0^T [out=4096][in=1024] fp16
__device__ __half g_W1h[1024u * 4096u];  // 8 MB, W1^T [out=1024][in=4096] fp16
__device__ __half g_Xh [8192u * 1024u];  // 16 MB, fp16 x
__device__ __half g_Hh [8192u * 4096u];  // 64 MB, fp16 gelu(h)

// ---------------- helpers ----------------
DEV uint32_t smem_u32(const void* p) { return (uint32_t)__cvta_generic_to_shared(p); }
DEV void cp_async16(uint32_t dst, const void* src) {
    asm volatile("cp.async.cg.shared.global [%0], [%1], 16;\n" :: "r"(dst), "l"(src));
}
DEV void cp_commit() { asm volatile("cp.async.commit_group;\n" ::: "memory"); }
template <int W> DEV void cp_wait() {
    asm volatile("cp.async.wait_group %0;\n" :: "n"(W) : "memory");
}
DEV void mma_f16(float* c, const uint32_t* a, const uint32_t b0, const uint32_t b1) {
    asm volatile(
        "mma.sync.aligned.m16n8k16.row.col.f32.f16.f16.f32 "
        "{%0,%1,%2,%3}, {%4,%5,%6,%7}, {%8,%9}, {%0,%1,%2,%3};\n"
        : "+f"(c[0]), "+f"(c[1]), "+f"(c[2]), "+f"(c[3])
        : "r"(a[0]), "r"(a[1]), "r"(a[2]), "r"(a[3]), "r"(b0), "r"(b1));
}
DEV void ldsm_x4(uint32_t* r, uint32_t addr) {
    asm volatile("ldmatrix.sync.aligned.m8n8.x4.shared.b16 {%0,%1,%2,%3}, [%4];"
                 : "=r"(r[0]), "=r"(r[1]), "=r"(r[2]), "=r"(r[3]) : "r"(addr));
}
// exact-erf gelu via the cheap erff polynomial path
DEV float gelu_exact(float x) {
    return 0.5f * x * (1.0f + erff(x * 0.70710678118654752f));
}

union H2x4 {
    uint4 u;
    __half2 h[4];
};

// ---------------- prologue kernel 1: x fp32 -> fp16 (pure HBM stream) --------
// Natural register count (~25) -> high occupancy; 1024 blocks x 256 thr x 4 uint4.
__global__ void __launch_bounds__(256)
k_convert(const float4* __restrict__ x) {
    const int bid = blockIdx.x;
    const int t = threadIdx.x;
    uint4* xh4 = reinterpret_cast<uint4*>(g_Xh);
#pragma unroll
    for (int kk = 0; kk < 4; kk++) {
        int idx = bid * 1024 + kk * 256 + t;       // < 1M
        float4 v0 = x[2 * idx];
        float4 v1 = x[2 * idx + 1];
        H2x4 o;
        o.h[0] = __floats2half2_rn(v0.x, v0.y);
        o.h[1] = __floats2half2_rn(v0.z, v0.w);
        o.h[2] = __floats2half2_rn(v1.x, v1.y);
        o.h[3] = __floats2half2_rn(v1.z, v1.w);
        xh4[idx] = o.u;
    }
}

// ---------------- prologue kernel 2: dedup'd TT weight builders --------------
// (Round-14 code verbatim — measured good; natural 160 regs is fine here.)
// blocks [0,256)    : W0^T for (p,q); bc once, 16 o-rows
// blocks [256,384)  : W1^T for (p,q); bc once, 8 o-rows
constexpr int WB_W0 = 256, WB_W1 = 128;
constexpr int WB_TOTAL = WB_W0 + WB_W1;

__global__ void __launch_bounds__(256)
k_build(const float* __restrict__ c0a, const float* __restrict__ c0b,
        const float* __restrict__ c0c,
        const float* __restrict__ c1a, const float* __restrict__ c1b,
        const float* __restrict__ c1c) {
    const int bid = blockIdx.x;
    const int t = threadIdx.x;

    if (bid < WB_W0) {
        // ---- W0t[(o*16+p)*16+q][(i*16+j)*8+k] = sum_r a[i,o,r] * bc[(r*16+j)*8+k]
        __shared__ float a_sh[1024], b_sh[1024], c_sh[64], bc[1024];
        const int pq = bid;
        const int p = pq >> 4, q = pq & 15;

        for (int idx = t; idx < 1024; idx += 256) {
            a_sh[idx] = c0a[idx];                            // a[(i*16+o)*8+r]
            b_sh[idx] = c0b[(idx >> 3) * 128 + p * 8 + (idx & 7)]; // b[(rj)*8+s]
        }
        if (t < 64) {                                        // c_sh[s*8+k]
            int s = t >> 3, k = t & 7;
            c_sh[t] = c0c[(s * 8 + k) * 16 + q];
        }
        __syncthreads();
        for (int idx = t; idx < 1024; idx += 256) {          // bc[(rj)*8+k]
            int rj = idx >> 3, k = idx & 7;
            float acc = 0.f;
#pragma unroll
            for (int s = 0; s < 8; s++) acc = fmaf(b_sh[rj * 8 + s], c_sh[s * 8 + k], acc);
            bc[idx] = acc;
        }
        __syncthreads();
#pragma unroll 1
        for (int o = 0; o < 16; o++) {
            const int m = (o * 16 + p) * 16 + q;
            float v[4];
#pragma unroll
            for (int d = 0; d < 4; d++) {
                int n = 4 * t + d;
                int i = n >> 7, j = (n >> 3) & 15, k = n & 7;
                float acc = 0.f;
#pragma unroll
                for (int r = 0; r < 8; r++)
                    acc = fmaf(a_sh[(i * 16 + o) * 8 + r], bc[(r * 16 + j) * 8 + k], acc);
                v[d] = acc;
            }
            __half2* dst = reinterpret_cast<__half2*>(&g_W0h[(size_t)m * 1024 + 4 * t]);
            dst[0] = __floats2half2_rn(v[0], v[1]);
            dst[1] = __floats2half2_rn(v[2], v[3]);
        }
    } else {
        // ---- W1t[(o*16+p)*8+q][(i*16+j)*16+k] = sum_r a[i,o,r] * bc[(r*16+j)*16+k]
        __shared__ float a_sh1[1024], b_sh1[1024], c_sh1[128], bc1[2048];
        const int pq = bid - WB_W0;
        const int p = pq >> 3, q = pq & 7;

        for (int idx = t; idx < 1024; idx += 256) {
            a_sh1[idx] = c1a[idx];                           // a[(i*8+o)*8+r]
            b_sh1[idx] = c1b[(idx >> 3) * 128 + p * 8 + (idx & 7)];
        }
        if (t < 128) {                                       // c_sh[s*16+k]
            int s = t >> 4, k = t & 15;
            c_sh1[t] = c1c[(s * 16 + k) * 8 + q];
        }
        __syncthreads();
        for (int idx = t; idx < 2048; idx += 256) {          // bc[(rj)*16+k]
            int rj = idx >> 4, k = idx & 15;
            float acc = 0.f;
#pragma unroll
            for (int s = 0; s < 8; s++) acc = fmaf(b_sh1[rj * 8 + s], c_sh1[s * 16 + k], acc);
            bc1[idx] = acc;
        }
        __syncthreads();
        const int i = t >> 4, j = t & 15;                    // n = 16t + k
#pragma unroll 1
        for (int o = 0; o < 8; o++) {
            const int m = (o * 16 + p) * 8 + q;
            float v[16];
#pragma unroll
            for (int k = 0; k < 16; k++) {
                float acc = 0.f;
#pragma unroll
                for (int r = 0; r < 8; r++)
                    acc = fmaf(a_sh1[(i * 8 + o) * 8 + r], bc1[(r * 16 + j) * 16 + k], acc);
                v[k] = acc;
            }
            __half2* dst = reinterpret_cast<__half2*>(&g_W1h[(size_t)m * 4096 + 16 * t]);
#pragma unroll
            for (int d = 0; d < 8; d++)
                dst[d] = __floats2half2_rn(v[2 * d], v[2 * d + 1]);
        }
    }
}

// ---------------- fp16 GEMM: C = act(A @ B^T + bias) ----------------
// CTA tile 128(M) x 256(N), BK=64 halves, 3-stage cp.async ring.
// 256 threads = 8 warps in 2(M) x 4(N); warp tile 64x64 (acc 128 regs).
// At the legacy-HMMA instruction-rate ceiling; unchanged from Round 10-14 best.
constexpr int BM = 128, BN = 256, BKH = 64, STAGES = 3;
constexpr int STRW = 36;                               // 32 words + 4 pad
constexpr int ROWB = STRW * 4;                         // 144 B row stride
constexpr int A_WORDS = BM * STRW;                     // 4608
constexpr int B_WORDS = BN * STRW;                     // 9216
constexpr int STAGE_WORDS = A_WORDS + B_WORDS;         // 13824
constexpr int STAGE_BYTES = STAGE_WORDS * 4;           // 55296
constexpr uint32_t STAGE_LAST = 2u * STAGE_BYTES;
constexpr int GEMM_SMEM = STAGES * STAGE_BYTES;        // 165888 B

template <bool FUSE_GELU, bool HALF_OUT>
__global__ void __launch_bounds__(256, 1)
k_gemm_f16(const __half* __restrict__ A, const __half* __restrict__ Bg,
           const float* __restrict__ bias, void* __restrict__ Cv,
           int M, int N, int K) {
    extern __shared__ uint32_t smem_w[];
    const uint32_t sbase = smem_u32(smem_w);

    const int tid = threadIdx.x;
    const int m0 = blockIdx.y * BM;
    const int n0 = blockIdx.x * BN;
    const int lane = tid & 31;
    const int warp = tid >> 5;
    const int g = lane >> 2, tig = lane & 3;
    const int wm = (warp & 1) * 64;        // 2 warps in M
    const int wn = (warp >> 1) * 64;       // 4 warps in N

    const int T = K / BKH;

    // ---- cp.async mapping: 384 rows x 128B per stage = 3072 x 16B chunks ----
    const int r0 = tid >> 3;
    const int cwB = (tid & 7) * 16;                 // byte offset within row
    const __half* aNext = A + (size_t)(m0 + r0) * K + (tid & 7) * 8;
    const __half* bNext = Bg + (size_t)(n0 + r0) * K + (tid & 7) * 8;
    const uint32_t sa_off = (uint32_t)(r0 * ROWB) + (uint32_t)cwB;
    const uint32_t sb_off = (uint32_t)A_WORDS * 4u + sa_off;

    auto issue_at = [&](uint32_t stoff) {
        const uint32_t sa = sbase + stoff + sa_off;
        const uint32_t sb = sbase + stoff + sb_off;
#pragma unroll
        for (int i = 0; i < 4; i++)
            cp_async16(sa + (uint32_t)(32 * i * ROWB), aNext + (size_t)(32 * i) * K);
#pragma unroll
        for (int i = 0; i < 8; i++)
            cp_async16(sb + (uint32_t)(32 * i * ROWB), bNext + (size_t)(32 * i) * K);
        cp_commit();
        aNext += BKH;
        bNext += BKH;
    };

    // ldmatrix base addresses (stage 0)
    const uint32_t aLdsm = sbase
        + (uint32_t)((wm + (lane & 15)) * ROWB)
        + (uint32_t)((lane >> 4) * 16);
    const uint32_t bLdsm = sbase + (uint32_t)A_WORDS * 4u
        + (uint32_t)((wn + ((lane >> 4) << 3) + (lane & 7)) * ROWB)
        + (uint32_t)(((lane >> 3) & 1) * 16);

    float acc[4][8][4];
#pragma unroll
    for (int mi = 0; mi < 4; mi++)
#pragma unroll
        for (int ni = 0; ni < 8; ni++)
#pragma unroll
            for (int q = 0; q < 4; q++) acc[mi][ni][q] = 0.f;

    issue_at(0);
    issue_at(STAGE_BYTES);

    uint32_t stoff_i = STAGE_LAST;    // smem offset for next issue (stage t+2)
    uint32_t stoff_c = 0;             // smem offset for current compute (stage t)

    uint32_t af[2][4][4];             // double-buffered A frags (4 m16k16)
    uint32_t bq[2][4][4];             // double-buffered B frags (8 n8k16)

    for (int t = 0; t < T; ++t) {
        cp_wait<1>();                 // stage t landed
        __syncthreads();              // all reads of the buffer being refilled done

        const uint32_t aS = aLdsm + stoff_c;
        const uint32_t bS = bLdsm + stoff_c;
        stoff_c = (stoff_c == STAGE_LAST) ? 0u : stoff_c + (uint32_t)STAGE_BYTES;

        // prime k16=0 fragments immediately after the barrier
#pragma unroll
        for (int nip = 0; nip < 4; ++nip)
            ldsm_x4(bq[0][nip], bS + (uint32_t)(nip * 16 * ROWB));
#pragma unroll
        for (int mi = 0; mi < 4; ++mi)
            ldsm_x4(af[0][mi], aS + (uint32_t)(mi * 16 * ROWB));

        if (t + 2 < T) issue_at(stoff_i);
        stoff_i = (stoff_i == STAGE_LAST) ? 0u : stoff_i + (uint32_t)STAGE_BYTES;

#pragma unroll
        for (int k16 = 0; k16 < 4; ++k16) {
            const int cur = k16 & 1, nxt = cur ^ 1;
            if (k16 < 3) {            // prefetch next k16's fragments
                const uint32_t kb = (uint32_t)((k16 + 1) * 32);
#pragma unroll
                for (int nip = 0; nip < 4; ++nip)
                    ldsm_x4(bq[nxt][nip], bS + (uint32_t)(nip * 16 * ROWB) + kb);
#pragma unroll
                for (int mi = 0; mi < 4; ++mi)
                    ldsm_x4(af[nxt][mi], aS + (uint32_t)(mi * 16 * ROWB) + kb);
            }
#pragma unroll
            for (int mi = 0; mi < 4; ++mi)
#pragma unroll
                for (int ni = 0; ni < 8; ++ni)
                    mma_f16(acc[mi][ni], af[cur][mi], bq[cur][ni >> 1][2 * (ni & 1)],
                            bq[cur][ni >> 1][2 * (ni & 1) + 1]);
        }
    }

    // ---- epilogue ----
#pragma unroll
    for (int mi = 0; mi < 4; ++mi) {
        const int row = m0 + wm + mi * 16 + g;
#pragma unroll
        for (int ni = 0; ni < 8; ++ni) {
            const int col = n0 + wn + ni * 8 + tig * 2;
            const float bv0 = bias[col], bv1 = bias[col + 1];
            float v00 = acc[mi][ni][0] + bv0;
            float v01 = acc[mi][ni][1] + bv1;
            float v10 = acc[mi][ni][2] + bv0;
            float v11 = acc[mi][ni][3] + bv1;
            if (FUSE_GELU) {
                v00 = gelu_exact(v00);
                v01 = gelu_exact(v01);
                v10 = gelu_exact(v10);
                v11 = gelu_exact(v11);
            }
            if (HALF_OUT) {
                __half* C = (__half*)Cv;
                *reinterpret_cast<__half2*>(&C[(size_t)row * N + col]) =
                    __floats2half2_rn(v00, v01);
                *reinterpret_cast<__half2*>(&C[(size_t)(row + 8) * N + col]) =
                    __floats2half2_rn(v10, v11);
            } else {
                float* C = (float*)Cv;
                *reinterpret_cast<float2*>(&C[(size_t)row * N + col])       = make_float2(v00, v01);
                *reinterpret_cast<float2*>(&C[(size_t)(row + 8) * N + col]) = make_float2(v10, v11);
            }
        }
    }
}

// ---------------- launch ----------------
extern "C" void kernel_launch(void* const* d_in, const int* in_sizes, int n_in,
                              void* d_out, int out_size) {
    const float* x   = (const float*)d_in[0];
    const float* c0a = (const float*)d_in[1];
    const float* c0b = (const float*)d_in[2];
    const float* c0c = (const float*)d_in[3];
    const float* b0  = (const float*)d_in[4];
    const float* c1a = (const float*)d_in[5];
    const float* c1b = (const float*)d_in[6];
    const float* c1c = (const float*)d_in[7];
    const float* b1  = (const float*)d_in[8];
    float* out = (float*)d_out;

    void *pW0, *pW1, *pXh, *pHh;
    cudaGetSymbolAddress(&pW0, g_W0h);
    cudaGetSymbolAddress(&pW1, g_W1h);
    cudaGetSymbolAddress(&pXh, g_Xh);
    cudaGetSymbolAddress(&pHh, g_Hh);
    __half* W0h = (__half*)pW0;
    __half* W1h = (__half*)pW1;
    __half* Xh  = (__half*)pXh;
    __half* Hh  = (__half*)pHh;

    cudaFuncSetAttribute(k_gemm_f16<true, true>,
                         cudaFuncAttributeMaxDynamicSharedMemorySize, GEMM_SMEM);
    cudaFuncSetAttribute(k_gemm_f16<false, false>,
                         cudaFuncAttributeMaxDynamicSharedMemorySize, GEMM_SMEM);

    // 1a) weight builders (dedup'd, natural regs; small grid)
    k_build<<<WB_TOTAL, 256>>>(c0a, c0b, c0c, c1a, c1b, c1c);
    // 1b) x -> fp16 (pure HBM stream at natural ~25 regs -> high occupancy)
    k_convert<<<1024, 256>>>((const float4*)x);
    // 2) Hh = fp16(gelu(Xh @ W0h^T + b0))   [8192 x 4096]
    k_gemm_f16<true, true><<<dim3(4096 / BN, 8192 / BM), 256, GEMM_SMEM>>>(
        Xh, W0h, b0, Hh, 8192, 4096, 1024);
    // 3) out = Hh @ W1h^T + b1              [8192 x 1024] fp32
    k_gemm_f16<false, false><<<dim3(1024 / BN, 8192 / BM), 256, GEMM_SMEM>>>(
        Hh, W1h, b1, out, 8192, 1024, 4096);
}